// round 4
// baseline (speedup 1.0000x reference)
#include <cuda_runtime.h>
#include <math.h>

// Problem constants
#define NN 50000
#define EE 800000
#define NE 850000      // EE + NN self loops
#define FIN 32
#define CDIM 16
#define DIN 48
#define CC 64
#define H0 2

// ---------------- device scratch (allocation-free rule: __device__ globals) ---------
__device__ float g_h0[NN * 128];      // layer0 node features [N,2,64]
__device__ float g_as0[NN * 2];
__device__ float g_ad0[NN * 2];
__device__ float g_ex0[NE * 2];
__device__ float g_den0[NN * 2];      // becomes 1/denom after kinv0
__device__ float g_agg0[NN * 128];
__device__ float g_h1[NN * 64];
__device__ float g_as1[NN];
__device__ float g_ad1[NN];
__device__ float g_ex1[NE];
__device__ float g_den1[NN];

// vector reduction-add to global (sm_90+)
__device__ __forceinline__ void red_add_v4(float* addr, float a, float b, float c, float d) {
    asm volatile("red.global.add.v4.f32 [%0], {%1,%2,%3,%4};"
                 :: "l"(addr), "f"(a), "f"(b), "f"(c), "f"(d) : "memory");
}

// ---------------- init: zero denominators + agg0, out = b1 broadcast ---------------
__global__ void kinit(float* __restrict__ out, const float* __restrict__ b1) {
    int i = blockIdx.x * blockDim.x + threadIdx.x;
    int stride = gridDim.x * blockDim.x;
    for (int k = i; k < NN * 128; k += stride) g_agg0[k] = 0.f;
    for (int k = i; k < NN * 64; k += stride) out[k] = b1[k & 63];
    for (int k = i; k < NN * 2; k += stride) g_den0[k] = 0.f;
    for (int k = i; k < NN; k += stride) g_den1[k] = 0.f;
}

// ---------------- K1: h0 = concat(base, emb[cid]) @ W0 ; alpha_s0 / alpha_d0 -------
#define NPB1 32
__global__ void k1(const float* __restrict__ x, const float* __restrict__ emb,
                   const float* __restrict__ W0, const float* __restrict__ a_src0,
                   const float* __restrict__ a_dst0) {
    __shared__ float sW[DIN * 128];
    __shared__ float sIn[DIN];
    __shared__ float red[8];
    int j = threadIdx.x;  // 0..127
    for (int t = j; t < DIN * 128; t += 128) sW[t] = W0[t];
    float aS = a_src0[j];   // [2,64] flattened == j
    float aD = a_dst0[j];
    __syncthreads();

    int base = blockIdx.x * NPB1;
    for (int it = 0; it < NPB1; ++it) {
        int n = base + it;
        if (n >= NN) break;                 // block-uniform
        if (j < FIN) {
            sIn[j] = x[n * 33 + j];
        } else if (j < DIN) {
            int cid = (int)x[n * 33 + FIN];
            sIn[j] = emb[cid * CDIM + (j - FIN)];
        }
        __syncthreads();
        float acc = 0.f;
        #pragma unroll
        for (int k = 0; k < DIN; ++k) acc += sIn[k] * sW[k * 128 + j];
        g_h0[n * 128 + j] = acc;

        float vs = acc * aS, vd = acc * aD;
        #pragma unroll
        for (int o = 16; o > 0; o >>= 1) {
            vs += __shfl_xor_sync(0xffffffffu, vs, o);
            vd += __shfl_xor_sync(0xffffffffu, vd, o);
        }
        if ((j & 31) == 0) { red[j >> 5] = vs; red[4 + (j >> 5)] = vd; }
        __syncthreads();
        if (j == 0) {
            g_as0[n * 2 + 0] = red[0] + red[1];
            g_as0[n * 2 + 1] = red[2] + red[3];
            g_ad0[n * 2 + 0] = red[4] + red[5];
            g_ad0[n * 2 + 1] = red[6] + red[7];
        }
        __syncthreads();
    }
}

// ---------------- K2a: layer0 edge logits, exp, denom accumulate -------------------
__global__ void k2a(const int* __restrict__ ei) {
    int e = blockIdx.x * blockDim.x + threadIdx.x;
    if (e >= NE) return;
    int src, dst;
    if (e < EE) { src = ei[e]; dst = ei[EE + e]; }
    else        { src = dst = e - EE; }
    #pragma unroll
    for (int h = 0; h < H0; ++h) {
        float v = g_as0[src * 2 + h] + g_ad0[dst * 2 + h];
        v = v > 0.f ? v : 0.2f * v;
        float ex = expf(v);
        g_ex0[e * 2 + h] = ex;
        atomicAdd(&g_den0[dst * 2 + h], ex);
    }
}

__global__ void kinv0() {
    int i = blockIdx.x * blockDim.x + threadIdx.x;
    if (i < NN * 2) g_den0[i] = 1.f / g_den0[i];
}

// ---------------- K2b: layer0 edge aggregation (warp per edge) ---------------------
__global__ void k2b(const int* __restrict__ ei) {
    int gid = blockIdx.x * blockDim.x + threadIdx.x;
    int e = gid >> 5;
    if (e >= NE) return;
    int lane = gid & 31;
    int src, dst;
    if (e < EE) { src = ei[e]; dst = ei[EE + e]; }
    else        { src = dst = e - EE; }
    int head = lane >> 4;  // lanes 0-15: head0 cols 0..63, lanes 16-31: head1
    float alpha = g_ex0[e * 2 + head] * g_den0[dst * 2 + head];
    const float4 h = *(const float4*)(g_h0 + src * 128 + lane * 4);
    red_add_v4(g_agg0 + dst * 128 + lane * 4,
               h.x * alpha, h.y * alpha, h.z * alpha, h.w * alpha);
}

// ---------------- K4: mean heads + b0, LayerNorm, ELU, GEMM W1, alphas -------------
#define NPB4 32
__device__ __forceinline__ float2 gsum64x2(float a, float b, float* s4, int jj) {
    #pragma unroll
    for (int o = 16; o > 0; o >>= 1) {
        a += __shfl_xor_sync(0xffffffffu, a, o);
        b += __shfl_xor_sync(0xffffffffu, b, o);
    }
    if ((jj & 31) == 0) { s4[jj >> 5] = a; s4[2 + (jj >> 5)] = b; }
    __syncthreads();
    float2 r = make_float2(s4[0] + s4[1], s4[2] + s4[3]);
    __syncthreads();
    return r;
}

__global__ void k4(const float* __restrict__ b0, const float* __restrict__ lng,
                   const float* __restrict__ lnb, const float* __restrict__ W1,
                   const float* __restrict__ a_s1, const float* __restrict__ a_d1) {
    __shared__ float sW[64 * 64];
    __shared__ float sX[4][64];
    __shared__ float sred[4][4];
    int tid = threadIdx.x;        // 256 threads: 4 groups of 64
    int gg = tid >> 6, jj = tid & 63;
    for (int t = tid; t < 64 * 64; t += 256) sW[t] = W1[t];
    float aS = a_s1[jj], aD = a_d1[jj];
    float bb = b0[jj], g = lng[jj], be = lnb[jj];
    __syncthreads();

    int base = blockIdx.x * NPB4;
    for (int it = 0; it < NPB4 / 4; ++it) {
        int n = base + it * 4 + gg;
        bool valid = (n < NN);
        float y = 0.f;
        if (valid) y = 0.5f * (g_agg0[n * 128 + jj] + g_agg0[n * 128 + 64 + jj]) + bb;
        float2 r = gsum64x2(y, y * y, sred[gg], jj);
        float mu = r.x * (1.f / 64.f);
        float var = r.y * (1.f / 64.f) - mu * mu;
        float xn = (y - mu) * rsqrtf(var + 1e-5f) * g + be;
        float ev = xn > 0.f ? xn : expm1f(xn);
        sX[gg][jj] = ev;
        __syncthreads();
        float acc = 0.f;
        #pragma unroll
        for (int k = 0; k < 64; ++k) acc += sX[gg][k] * sW[k * 64 + jj];
        float2 r2 = gsum64x2(acc * aS, acc * aD, sred[gg], jj);
        if (valid) {
            g_h1[n * 64 + jj] = acc;
            if (jj == 0) { g_as1[n] = r2.x; g_ad1[n] = r2.y; }
        }
        __syncthreads();
    }
}

// ---------------- K5a: layer1 edge logits -----------------------------------------
__global__ void k5a(const int* __restrict__ ei) {
    int e = blockIdx.x * blockDim.x + threadIdx.x;
    if (e >= NE) return;
    int src, dst;
    if (e < EE) { src = ei[e]; dst = ei[EE + e]; }
    else        { src = dst = e - EE; }
    float v = g_as1[src] + g_ad1[dst];
    v = v > 0.f ? v : 0.2f * v;
    float ex = expf(v);
    g_ex1[e] = ex;
    atomicAdd(&g_den1[dst], ex);
}

__global__ void kinv1() {
    int i = blockIdx.x * blockDim.x + threadIdx.x;
    if (i < NN) g_den1[i] = 1.f / g_den1[i];
}

// ---------------- K5b: layer1 edge aggregation into d_out (16 lanes/edge) ----------
__global__ void k5b(const int* __restrict__ ei, float* __restrict__ out) {
    int gid = blockIdx.x * blockDim.x + threadIdx.x;
    int e = gid >> 4;
    if (e >= NE) return;
    int l = gid & 15;
    int src, dst;
    if (e < EE) { src = ei[e]; dst = ei[EE + e]; }
    else        { src = dst = e - EE; }
    float alpha = g_ex1[e] * g_den1[dst];
    const float4 h = *(const float4*)(g_h1 + src * 64 + l * 4);
    red_add_v4(out + dst * 64 + l * 4,
               h.x * alpha, h.y * alpha, h.z * alpha, h.w * alpha);
}

// ---------------- launch -----------------------------------------------------------
extern "C" void kernel_launch(void* const* d_in, const int* in_sizes, int n_in,
                              void* d_out, int out_size) {
    const float* x      = (const float*)d_in[0];
    const int*   ei     = (const int*)  d_in[1];
    const float* emb    = (const float*)d_in[2];
    const float* W0     = (const float*)d_in[3];
    const float* a_src0 = (const float*)d_in[4];
    const float* a_dst0 = (const float*)d_in[5];
    const float* b0     = (const float*)d_in[6];
    const float* ln_g   = (const float*)d_in[7];
    const float* ln_b   = (const float*)d_in[8];
    const float* W1     = (const float*)d_in[9];
    const float* a_src1 = (const float*)d_in[10];
    const float* a_dst1 = (const float*)d_in[11];
    const float* b1     = (const float*)d_in[12];
    float* out = (float*)d_out;

    kinit<<<2048, 256>>>(out, b1);
    k1<<<(NN + NPB1 - 1) / NPB1, 128>>>(x, emb, W0, a_src0, a_dst0);
    k2a<<<(NE + 255) / 256, 256>>>(ei);
    kinv0<<<(NN * 2 + 255) / 256, 256>>>();
    k2b<<<(NE * 32 + 255) / 256, 256>>>(ei);
    k4<<<(NN + NPB4 - 1) / NPB4, 256>>>(b0, ln_g, ln_b, W1, a_src1, a_dst1);
    k5a<<<(NE + 255) / 256, 256>>>(ei);
    kinv1<<<(NN + 255) / 256, 256>>>();
    k5b<<<(NE * 16 + 255) / 256, 256>>>(ei, out);
}